// round 16
// baseline (speedup 1.0000x reference)
#include <cuda_runtime.h>
#include <cuda_fp16.h>
#include <cstdint>

// ---------------------------------------------------------------------------
// LinearDecoder: mean_out = mean @ W^T + b ; logv = log((W*W) @ exp(logvar))
// B=131072, XDIM=128, YDIM=512. fp16 mma.sync, f32 accumulate.
// 512 threads/CTA, two 8-warp groups (R14 proven skeleton).
// A path: LDG.128-direct prefetch in two register halves -> cvt -> STS
// (staging SMEM round-trip eliminated). B resident in SMEM with row
// permutation -> STG.128 epilogue. Output: [mean_out][logv], f32.
// ---------------------------------------------------------------------------

#define DEVINL __device__ __forceinline__

static constexpr int BATCH    = 131072;
static constexpr int XD       = 128;            // K
static constexpr int YD       = 512;            // total N
static constexpr int MT       = 128;            // M tile (two 64-row groups)
static constexpr int GM       = 64;             // rows per group
static constexpr int NT       = 256;            // N per CTA
static constexpr int M_TILES  = BATCH / MT;     // 1024
static constexpr int GX       = 37;             // 37*2*2 = 148 CTAs = 1 wave
static constexpr int NTHREADS = 512;            // 16 warps: 2 groups x (2m x 4n)

// fp16 rows padded to 136 halves (272 B): ldmatrix conflict-free.
static constexpr int ROW_H   = 136;
static constexpr int ROW_B   = ROW_H * 2;       // 272
static constexpr int SM_B    = 0;                               // half[256][136]
static constexpr int SM_BIAS = SM_B + NT * ROW_B;               // 69632 (+1024)
static constexpr int SM_A    = SM_BIAS + 1024;                  // 70656
static constexpr int A_BUF   = GM * ROW_B;                      // 17408
static constexpr int SM_TOTAL= SM_A + 4 * A_BUF;                // 140288 bytes

// B-row permutation: smem logical row r holds W physical row p(r); makes each
// thread's 4 epilogue values land on 4 consecutive physical output columns.
DEVINL int bperm(int r) {
    return (r & ~15) | (((r >> 1) & 3) << 2) | (((r >> 3) & 1) << 1) | (r & 1);
}

// ---------------- PTX helpers ----------------
DEVINL uint32_t smem_u32(const void* p) {
    uint32_t a;
    asm("{ .reg .u64 t; cvta.to.shared.u64 t, %1; cvt.u32.u64 %0, t; }" : "=r"(a) : "l"(p));
    return a;
}
DEVINL void ldm4(uint32_t* r, uint32_t addr) {
    asm volatile("ldmatrix.sync.aligned.m8n8.x4.shared.b16 {%0,%1,%2,%3}, [%4];"
                 : "=r"(r[0]), "=r"(r[1]), "=r"(r[2]), "=r"(r[3]) : "r"(addr));
}
DEVINL void mma_f16(float* c, const uint32_t* a, uint32_t b0, uint32_t b1) {
    asm volatile("mma.sync.aligned.m16n8k16.row.col.f32.f16.f16.f32 "
                 "{%0,%1,%2,%3}, {%4,%5,%6,%7}, {%8,%9}, {%0,%1,%2,%3};"
                 : "+f"(c[0]), "+f"(c[1]), "+f"(c[2]), "+f"(c[3])
                 : "r"(a[0]), "r"(a[1]), "r"(a[2]), "r"(a[3]), "r"(b0), "r"(b1));
}
#define GBAR(id)     asm volatile("bar.sync %0, %1;" :: "r"(id), "r"(256) : "memory")

DEVINL uint32_t h2u(__half2 h) { return *reinterpret_cast<uint32_t*>(&h); }

// convert one float4 (optionally exp'd) to 4 halves, store 8B to smem
DEVINL void cvt_st(char* dst, int byte_off, float4 v, int branch) {
    if (branch) { v.x = __expf(v.x); v.y = __expf(v.y); v.z = __expf(v.z); v.w = __expf(v.w); }
    uint2 u;
    u.x = h2u(__floats2half2_rn(v.x, v.y));
    u.y = h2u(__floats2half2_rn(v.z, v.w));
    *reinterpret_cast<uint2*>(dst + byte_off) = u;
}

// ---------------- kernel ----------------
__global__ void __launch_bounds__(NTHREADS, 1)
lindec_kernel(const float* __restrict__ mean, const float* __restrict__ logvar,
              const float* __restrict__ W, const float* __restrict__ bias,
              float* __restrict__ out) {
    extern __shared__ char smem[];
    const uint32_t sb = smem_u32(smem);
    const int tid  = threadIdx.x;
    const int wid  = tid >> 5;
    const int lane = tid & 31;
    const int branch = blockIdx.z;          // 0: mean, 1: variance
    const int n0g    = blockIdx.y * NT;     // global N offset

    const int g    = wid >> 3;              // group 0/1 -> M rows [64g, 64g+64)
    const int gtid = tid & 255;
    const int gw   = wid & 7;
    const int wm   = (gw >> 2) * 32;        // warp M origin within group
    const int wn   = (gw & 3) * 64;         // warp N origin

    const float* Asrc = branch ? logvar : mean;
    float* outb = out + (size_t)branch * BATCH * YD + n0g;

    char* abuf_c = smem + SM_A + g * 2 * A_BUF;

    // ---- prologue: resident B = fp16(W[perm]) (squared for branch 1) ----
    {
        const float* Wp = W + (size_t)n0g * XD;
#pragma unroll 4
        for (int idx = tid; idx < NT * (XD / 4); idx += NTHREADS) {
            const int r = idx >> 5, c4 = idx & 31;
            const int pr = bperm(r);
            float4 v = *reinterpret_cast<const float4*>(Wp + (size_t)pr * XD + c4 * 4);
            if (branch) { v.x *= v.x; v.y *= v.y; v.z *= v.z; v.w *= v.w; }
            uint2 u;
            u.x = h2u(__floats2half2_rn(v.x, v.y));
            u.y = h2u(__floats2half2_rn(v.z, v.w));
            *reinterpret_cast<uint2*>(smem + SM_B + r * ROW_B + c4 * 8) = u;
        }
        if (branch == 0)
            for (int n = tid; n < NT; n += NTHREADS)   // bias in PHYSICAL order
                reinterpret_cast<float*>(smem + SM_BIAS)[n] = bias[n0g + n];
    }

    // ---- prologue: tile 0 A half for this group (direct LDG) ----
    {
        const float* src = Asrc + ((size_t)blockIdx.x * MT + g * GM) * XD;
#pragma unroll
        for (int i = 0; i < 8; i++) {
            const int idx = gtid + 256 * i;            // 0..2047 float4s, 64 rows
            float4 v = __ldg(reinterpret_cast<const float4*>(src) + idx);
            const int r = idx >> 5, c4 = idx & 31;
            cvt_st(abuf_c, r * ROW_B + c4 * 8, v, branch);
        }
    }
    __syncthreads();

    // ldmatrix per-lane addressing
    const int a_r = lane & 15;
    const int a_c = (lane >> 4) * 8;
    const int b_r = (lane & 7) + ((lane >> 4) << 3);
    const int b_c = ((lane >> 3) & 1) * 8;

    uint32_t baddr[4];
#pragma unroll
    for (int nt = 0; nt < 4; nt++)
        baddr[nt] = sb + SM_B + (wn + nt * 16 + b_r) * ROW_B + b_c * 2;

    const float* bsm = reinterpret_cast<const float*>(smem + SM_BIAS);

    int it = 0;
    for (int t = blockIdx.x; t < M_TILES; t += GX, ++it) {
        const int cur = it & 1;
        const bool has_next = (t + GX) < M_TILES;
        const float* nsrc = Asrc + ((size_t)(t + GX) * MT + g * GM) * XD;

        // ---- prefetch half-0 of next tile (rows 0..31) into registers ----
        float4 pre[4];
        if (has_next) {
#pragma unroll
            for (int i = 0; i < 4; i++)
                pre[i] = __ldg(reinterpret_cast<const float4*>(nsrc) + gtid + 256 * i);
        }

        // ---- MMA: 32x64 per warp, K=128 in 8 k16 steps ----
        float acc[2][8][4];
#pragma unroll
        for (int mi = 0; mi < 2; mi++)
#pragma unroll
            for (int ni = 0; ni < 8; ni++)
#pragma unroll
                for (int q = 0; q < 4; q++) acc[mi][ni][q] = 0.f;

        uint32_t aaddr[2];
#pragma unroll
        for (int mi = 0; mi < 2; mi++)
            aaddr[mi] = sb + SM_A + (g * 2 + cur) * A_BUF
                      + (wm + mi * 16 + a_r) * ROW_B + a_c * 2;

#pragma unroll
        for (int k = 0; k < 8; k++) {
            uint32_t af[2][4], bf[4][4];
#pragma unroll
            for (int mi = 0; mi < 2; mi++) ldm4(af[mi], aaddr[mi] + k * 32);
#pragma unroll
            for (int nt = 0; nt < 4; nt++) ldm4(bf[nt], baddr[nt] + k * 32);
#pragma unroll
            for (int mi = 0; mi < 2; mi++)
#pragma unroll
                for (int ni = 0; ni < 8; ni++)
                    mma_f16(acc[mi][ni], af[mi],
                            bf[ni >> 1][(ni & 1) * 2], bf[ni >> 1][(ni & 1) * 2 + 1]);
        }

        // ---- store half-0 into next A buffer; prefetch half-1 (rows 32..63) ----
        if (has_next) {
            char* dst = abuf_c + (cur ^ 1) * A_BUF;
#pragma unroll
            for (int i = 0; i < 4; i++) {
                const int idx = gtid + 256 * i;
                const int r = idx >> 5, c4 = idx & 31;
                cvt_st(dst, r * ROW_B + c4 * 8, pre[i], branch);
            }
            const float* nsrc1 = nsrc + (size_t)32 * XD;
#pragma unroll
            for (int i = 0; i < 4; i++)
                pre[i] = __ldg(reinterpret_cast<const float4*>(nsrc1) + gtid + 256 * i);
        }

        // ---- epilogue: 4 consecutive physical cols per thread -> STG.128 ----
        {
            const size_t rbase = (size_t)t * MT + g * GM + wm + (lane >> 2);
#pragma unroll
            for (int mi = 0; mi < 2; mi++) {
                float* p0 = outb + (rbase + mi * 16) * YD;
                float* p1 = p0 + 8 * YD;
#pragma unroll
                for (int pr = 0; pr < 4; pr++) {
                    const int c = wn + pr * 16 + 4 * (lane & 3);
                    const int e = pr * 2, o = pr * 2 + 1;
                    float4 v0, v1;
                    v0.x = acc[mi][e][0]; v0.y = acc[mi][e][1];
                    v0.z = acc[mi][o][0]; v0.w = acc[mi][o][1];
                    v1.x = acc[mi][e][2]; v1.y = acc[mi][e][3];
                    v1.z = acc[mi][o][2]; v1.w = acc[mi][o][3];
                    if (branch == 0) {
                        const float4 bb = *reinterpret_cast<const float4*>(bsm + c);
                        v0.x += bb.x; v0.y += bb.y; v0.z += bb.z; v0.w += bb.w;
                        v1.x += bb.x; v1.y += bb.y; v1.z += bb.z; v1.w += bb.w;
                    } else {
                        v0.x = __logf(v0.x); v0.y = __logf(v0.y);
                        v0.z = __logf(v0.z); v0.w = __logf(v0.w);
                        v1.x = __logf(v1.x); v1.y = __logf(v1.y);
                        v1.z = __logf(v1.z); v1.w = __logf(v1.w);
                    }
                    *reinterpret_cast<float4*>(p0 + c) = v0;
                    *reinterpret_cast<float4*>(p1 + c) = v1;
                }
            }
        }

        // ---- store half-1 into next A buffer ----
        if (has_next) {
            char* dst = abuf_c + (cur ^ 1) * A_BUF;
#pragma unroll
            for (int i = 0; i < 4; i++) {
                const int idx = gtid + 256 * i;
                const int r = 32 + (idx >> 5), c4 = idx & 31;
                cvt_st(dst, r * ROW_B + c4 * 8, pre[i], branch);
            }
        }
        GBAR(1 + g);
    }
}

// ---------------- launch ----------------
extern "C" void kernel_launch(void* const* d_in, const int* in_sizes, int n_in,
                              void* d_out, int out_size) {
    const float* mean   = (const float*)d_in[0];
    const float* logvar = (const float*)d_in[1];
    const float* W      = (const float*)d_in[2];
    const float* bias   = (const float*)d_in[3];
    float* out = (float*)d_out;

    cudaFuncSetAttribute(lindec_kernel, cudaFuncAttributeMaxDynamicSharedMemorySize, SM_TOTAL);

    dim3 grid(GX, 2, 2);   // x: M-tile stride groups, y: N half, z: branch
    lindec_kernel<<<grid, NTHREADS, SM_TOTAL>>>(mean, logvar, W, bias, out);
}